// round 12
// baseline (speedup 1.0000x reference)
#include <cuda_runtime.h>
#include <cuda_bf16.h>
#include <math.h>
#include <stdint.h>

// ---------------------------------------------------------------------------
// GAT (2 layers) + output projection, GB300 sm_103a
// R11: fork/join streams inside the graph — CSR build chain runs concurrent
//      with layer-1 GEMM + elr (independent subgraphs). Coalesced 3-kernel
//      scan replaces the uncoalesced single-block scan.
// GEMM v4 (tf32 HMMA, cp.async 3-stage, 2 CTAs/SM) and single-pass agg
// unchanged (validated R10).
// ---------------------------------------------------------------------------

#define N_NODES 50000
#define N_EDGES 400000
#define NEG_SLOPE 0.1f
#define SCAN_BLOCKS ((N_NODES + 1023) / 1024)   // 49

// -------------------- device scratch (no allocation allowed) ---------------
__device__ float g_ft[N_NODES * 128];      // per-layer transformed features
__device__ float g_xcat[N_NODES * 256];    // [x1 | x2] concat buffer
__device__ float g_el[N_NODES * 4];
__device__ float g_er[N_NODES * 4];
__device__ int   g_cnt[N_NODES];
__device__ int   g_bsum[SCAN_BLOCKS];
__device__ int   g_rowptr[N_NODES + 1];
__device__ int   g_epos[N_EDGES];          // per-edge ticket within its dst row
__device__ int   g_csr_src[N_EDGES];
__device__ float g_csr_w[N_EDGES];

// -------------------- CSR build --------------------------------------------
__global__ void k_hist(const int* __restrict__ dst) {
    int e = blockIdx.x * blockDim.x + threadIdx.x;
    if (e < N_EDGES) g_epos[e] = atomicAdd(&g_cnt[dst[e]], 1);
}

// coalesced 3-phase exclusive scan of g_cnt -> g_rowptr
__global__ void k_scan1() {
    __shared__ int sh[1024];
    int t = threadIdx.x;
    int i = blockIdx.x * 1024 + t;
    int v = (i < N_NODES) ? g_cnt[i] : 0;
    sh[t] = v;
    __syncthreads();
    for (int off = 1; off < 1024; off <<= 1) {
        int u = (t >= off) ? sh[t - off] : 0;
        __syncthreads();
        sh[t] += u;
        __syncthreads();
    }
    if (i < N_NODES) g_rowptr[i] = sh[t] - v;      // exclusive within block
    if (t == 1023) g_bsum[blockIdx.x] = sh[1023];  // block total
}

__global__ void k_scan2() {
    if (threadIdx.x == 0) {
        int run = 0;
        for (int b = 0; b < SCAN_BLOCKS; b++) {
            int v = g_bsum[b];
            g_bsum[b] = run;
            run += v;
        }
    }
}

__global__ void k_scan3() {
    int t = threadIdx.x;
    int i = blockIdx.x * 1024 + t;
    if (i < N_NODES) g_rowptr[i] += g_bsum[blockIdx.x];
    if (i == 0) g_rowptr[N_NODES] = N_EDGES;       // total is a known constant
}

__global__ void k_scatter(const int* __restrict__ src, const int* __restrict__ dst,
                          const float* __restrict__ w) {
    int e = blockIdx.x * blockDim.x + threadIdx.x;
    if (e >= N_EDGES) return;
    int pos = g_rowptr[dst[e]] + g_epos[e];
    g_csr_src[pos] = src[e];
    g_csr_w[pos]   = w[e];
}

// -------------------- tf32 tensor-core GEMM (cp.async pipeline) ------------
// C[M,128] = A[M,K] @ B[K,128] (+bias), K multiple of 32.
// BM=128, BN=128, BK=32, 256 threads (8 warps, 4Mx2N), warp tile 32x64.
// 3-stage cp.async pipeline, ONE __syncthreads per tile, 2 CTAs/SM.

#define GEMM_THREADS 256
#define AS_STRIDE 36            // words per A row  (+4 pad, 16B-aligned)
#define BS_STRIDE 136           // words per B row  (+8 pad, 16B-aligned)
#define ASZ_W (128 * AS_STRIDE) // 4608
#define BSZ_W (32 * BS_STRIDE)  // 4352
#define STAGE_W (ASZ_W + BSZ_W) // 8960 words = 35840 B
#define N_STAGES 3
#define GEMM_SMEM (N_STAGES * STAGE_W * 4)   // 107520 B per CTA

__device__ __forceinline__ uint32_t f2tf32(float x) {
    uint32_t r;
    asm("cvt.rna.tf32.f32 %0, %1;" : "=r"(r) : "f"(x));
    return r;
}

__device__ __forceinline__ void mma8(float* c, const uint32_t* a,
                                     uint32_t b0, uint32_t b1) {
    asm volatile(
        "mma.sync.aligned.m16n8k8.row.col.f32.tf32.tf32.f32 "
        "{%0,%1,%2,%3}, {%4,%5,%6,%7}, {%8,%9}, {%0,%1,%2,%3};"
        : "+f"(c[0]), "+f"(c[1]), "+f"(c[2]), "+f"(c[3])
        : "r"(a[0]), "r"(a[1]), "r"(a[2]), "r"(a[3]), "r"(b0), "r"(b1));
}

__device__ __forceinline__ uint32_t cvta_shared(const void* p) {
    uint32_t a;
    asm("{ .reg .u64 t; cvta.to.shared.u64 t, %1; cvt.u32.u64 %0, t; }"
        : "=r"(a) : "l"(p));
    return a;
}

__device__ __forceinline__ void cp16(uint32_t dst, const void* src, int sz) {
    asm volatile("cp.async.cg.shared.global [%0], [%1], 16, %2;"
                 :: "r"(dst), "l"(src), "r"(sz));
}

__global__ __launch_bounds__(GEMM_THREADS, 2) void k_gemm_tf32(
    const float* __restrict__ A, int lda,
    const float* __restrict__ B,
    const float* __restrict__ bias,
    float* __restrict__ C, int ldc,
    int M, int K)
{
    extern __shared__ float smem[];
    const uint32_t sbase = cvta_shared(smem);

    const int tid  = threadIdx.x;
    const int lane = tid & 31;
    const int wid  = tid >> 5;
    const int warp_m = (wid & 3) * 32;     // 4 warps along M
    const int warp_n = (wid >> 2) * 64;    // 2 warps along N
    const int g  = lane >> 2;              // groupID (0..7)
    const int t4 = lane & 3;               // threadID_in_group
    const int row0 = blockIdx.x * 128;

    // per-thread cp.async coordinates (4 x 16B chunks each for A and B)
    int a_row[4], a_kq[4], b_row[4], b_c4[4];
    uint32_t a_dst[4], b_dst[4];
#pragma unroll
    for (int u = 0; u < 4; u++) {
        int c = tid + u * GEMM_THREADS;    // 0..1023
        a_row[u] = c >> 3;  a_kq[u] = c & 7;
        b_row[u] = c >> 5;  b_c4[u] = c & 31;
        a_dst[u] = sbase + (a_row[u] * AS_STRIDE + a_kq[u] * 4) * 4;
        b_dst[u] = sbase + (ASZ_W + b_row[u] * BS_STRIDE + b_c4[u] * 4) * 4;
    }

#define ISSUE_TILE(K0, st)                                                    \
    {                                                                         \
        uint32_t soff = (uint32_t)(st) * (STAGE_W * 4);                       \
        _Pragma("unroll")                                                     \
        for (int u = 0; u < 4; u++) {                                         \
            int gr = row0 + a_row[u];                                         \
            int ok = (gr < M) ? 16 : 0;                                       \
            const float* srcp = A + (size_t)min(gr, M - 1) * lda              \
                                  + (K0) + a_kq[u] * 4;                       \
            cp16(a_dst[u] + soff, srcp, ok);                                  \
        }                                                                     \
        _Pragma("unroll")                                                     \
        for (int u = 0; u < 4; u++) {                                         \
            const float* srcp = B + (size_t)((K0) + b_row[u]) * 128           \
                                  + b_c4[u] * 4;                              \
            cp16(b_dst[u] + soff, srcp, 16);                                  \
        }                                                                     \
        asm volatile("cp.async.commit_group;");                               \
    }

    float acc[2][8][4];
#pragma unroll
    for (int mt = 0; mt < 2; mt++)
#pragma unroll
        for (int nt = 0; nt < 8; nt++)
#pragma unroll
            for (int i = 0; i < 4; i++) acc[mt][nt][i] = 0.f;

    const int T = K >> 5;   // K/32 tiles

    // prologue: fill stages 0 and 1
    ISSUE_TILE(0, 0);
    if (T > 1) ISSUE_TILE(32, 1);

    for (int t = 0; t < T; t++) {
        if (t < T - 1) asm volatile("cp.async.wait_group 1;");
        else           asm volatile("cp.async.wait_group 0;");
        __syncthreads();
        // single barrier per tile: the ISSUE below writes stage
        // (t+2)%3 == (t-1)%3, whose readers (iteration t-1) all passed
        // this barrier already -> race-free without a second sync.

        const float* As_ = smem + (t % N_STAGES) * STAGE_W;
        const float* Bs_ = As_ + ASZ_W;

        if (t + 2 < T) ISSUE_TILE((t + 2) << 5, (t + 2) % N_STAGES);

#pragma unroll
        for (int ks = 0; ks < 4; ks++) {
            const int k8 = ks * 8;
            uint32_t a[2][4];
#pragma unroll
            for (int mt = 0; mt < 2; mt++) {
                int m_ = warp_m + mt * 16 + g;
                a[mt][0] = f2tf32(As_[m_ * AS_STRIDE + k8 + t4]);
                a[mt][1] = f2tf32(As_[(m_ + 8) * AS_STRIDE + k8 + t4]);
                a[mt][2] = f2tf32(As_[m_ * AS_STRIDE + k8 + t4 + 4]);
                a[mt][3] = f2tf32(As_[(m_ + 8) * AS_STRIDE + k8 + t4 + 4]);
            }
#pragma unroll
            for (int nt = 0; nt < 8; nt++) {
                int n_ = warp_n + nt * 8 + g;
                uint32_t b0 = f2tf32(Bs_[(k8 + t4) * BS_STRIDE + n_]);
                uint32_t b1 = f2tf32(Bs_[(k8 + t4 + 4) * BS_STRIDE + n_]);
                mma8(acc[0][nt], a[0], b0, b1);
                mma8(acc[1][nt], a[1], b0, b1);
            }
        }
    }

    // epilogue
#pragma unroll
    for (int nt = 0; nt < 8; nt++) {
        int cg = warp_n + nt * 8 + t4 * 2;
        float bv0 = bias ? bias[cg]     : 0.f;
        float bv1 = bias ? bias[cg + 1] : 0.f;
#pragma unroll
        for (int mt = 0; mt < 2; mt++) {
            int r = row0 + warp_m + mt * 16 + g;
            if (r < M) {
                float2 o; o.x = acc[mt][nt][0] + bv0; o.y = acc[mt][nt][1] + bv1;
                *(float2*)(C + (size_t)r * ldc + cg) = o;
            }
            if (r + 8 < M) {
                float2 o; o.x = acc[mt][nt][2] + bv0; o.y = acc[mt][nt][3] + bv1;
                *(float2*)(C + (size_t)(r + 8) * ldc + cg) = o;
            }
        }
    }
#undef ISSUE_TILE
}

// -------------------- el/er: warp-per-node attention dots ------------------
__global__ void k_elr(const float* __restrict__ al, const float* __restrict__ ar) {
    int wid  = threadIdx.x >> 5;
    int lane = threadIdx.x & 31;
    int n = blockIdx.x * 8 + wid;
    if (n >= N_NODES) return;
    float sl[4], sr[4];
#pragma unroll
    for (int j = 0; j < 4; j++) {
        float v = g_ft[n * 128 + j * 32 + lane];
        sl[j] = v * al[j * 32 + lane];
        sr[j] = v * ar[j * 32 + lane];
    }
#pragma unroll
    for (int off = 16; off >= 1; off >>= 1) {
#pragma unroll
        for (int j = 0; j < 4; j++) {
            sl[j] += __shfl_xor_sync(0xFFFFFFFFu, sl[j], off);
            sr[j] += __shfl_xor_sync(0xFFFFFFFFu, sr[j], off);
        }
    }
    if (lane == 0) {
#pragma unroll
        for (int j = 0; j < 4; j++) {
            g_el[n * 4 + j] = sl[j];
            g_er[n * 4 + j] = sr[j];
        }
    }
}

// -------------------- softmax + aggregate: single gather pass --------------
// Logits z = w * leaky(el+er) are O(0.5) by construction, so softmax without
// max-subtraction is exact: exp(z)/sum(exp(z)). Accumulate unnormalized
// acc = sum(exp(z)*ft[src]) and csum = sum(exp(z)) together; scale at end.
__device__ __forceinline__ float leaky(float z) {
    return z > 0.f ? z : NEG_SLOPE * z;
}

__global__ __launch_bounds__(256) void k_agg(float* __restrict__ xout, int ld, int coff) {
    __shared__ float sh_c[8][32];
    __shared__ int   sh_s[8][8];

    int wid  = threadIdx.x >> 5;
    int lane = threadIdx.x & 31;
    int n = blockIdx.x * 8 + wid;
    if (n >= N_NODES) return;

    int beg = g_rowptr[n];
    int end = g_rowptr[n + 1];

    if (beg == end) {
#pragma unroll
        for (int j = 0; j < 4; j++)
            xout[(size_t)n * ld + coff + j * 32 + lane] = 0.f;
        return;
    }

    int h  = lane & 3;     // head evaluated by this lane (coeff phase)
    int es = lane >> 2;    // edge slot (0..7)
    float erh = g_er[n * 4 + h];

    float csum = 0.f;
    float acc[4] = {0.f, 0.f, 0.f, 0.f};

    for (int b = beg; b < end; b += 8) {
        int e = b + es;
        float c = 0.f;
        int   sn = 0;
        if (e < end) {
            sn = g_csr_src[e];
            float z = g_csr_w[e] * leaky(g_el[sn * 4 + h] + erh);
            c = expf(z);
            csum += c;
        }
        sh_c[wid][lane] = c;                 // slot es, head h (lane = es*4+h)
        if (h == 0) sh_s[wid][es] = sn;
        __syncwarp();
        // fixed 8-deep unroll: invalid slots have c=0 (contribute nothing) and
        // s=0 (harmless L1-hit read). Batches 32 LDGs for high MLP.
#pragma unroll
        for (int k = 0; k < 8; k++) {
            int s = sh_s[wid][k];
            const float* fp = g_ft + (size_t)s * 128 + lane;
            acc[0] += sh_c[wid][k * 4 + 0] * fp[0];
            acc[1] += sh_c[wid][k * 4 + 1] * fp[32];
            acc[2] += sh_c[wid][k * 4 + 2] * fp[64];
            acc[3] += sh_c[wid][k * 4 + 3] * fp[96];
        }
        __syncwarp();
    }

    csum += __shfl_xor_sync(0xFFFFFFFFu, csum, 4);
    csum += __shfl_xor_sync(0xFFFFFFFFu, csum, 8);
    csum += __shfl_xor_sync(0xFFFFFFFFu, csum, 16);
    float inv[4];
#pragma unroll
    for (int j = 0; j < 4; j++)
        inv[j] = 1.f / __shfl_sync(0xFFFFFFFFu, csum, j);

#pragma unroll
    for (int j = 0; j < 4; j++)
        xout[(size_t)n * ld + coff + j * 32 + lane] = fmaxf(acc[j] * inv[j], 0.f);
}

// -------------------- host launch ------------------------------------------
// Fork/join: CSR build (side stream) runs concurrent with layer-1 GEMM+elr.
// Stream/events are created ONCE, on the first (un-captured correctness)
// call, so no resource-creation API runs during graph capture. The enqueued
// work is identical on every call.

extern "C" void kernel_launch(void* const* d_in, const int* in_sizes, int n_in,
                              void* d_out, int out_size) {
    const float* features = (const float*)d_in[0];
    const int*   src      = (const int*)  d_in[1];
    const int*   dst      = (const int*)  d_in[2];
    const float* w        = (const float*)d_in[3];
    const float* W1       = (const float*)d_in[4];
    const float* al1      = (const float*)d_in[5];
    const float* ar1      = (const float*)d_in[6];
    const float* W2       = (const float*)d_in[7];
    const float* al2      = (const float*)d_in[8];
    const float* ar2      = (const float*)d_in[9];
    const float* Wout     = (const float*)d_in[10];
    const float* bout     = (const float*)d_in[11];
    float* out = (float*)d_out;

    static cudaStream_t s1 = nullptr;
    static cudaEvent_t  ev_root = nullptr, ev_csr = nullptr;
    if (s1 == nullptr) {
        cudaStreamCreateWithFlags(&s1, cudaStreamNonBlocking);
        cudaEventCreateWithFlags(&ev_root, cudaEventDisableTiming);
        cudaEventCreateWithFlags(&ev_csr,  cudaEventDisableTiming);
        cudaFuncSetAttribute(k_gemm_tf32,
                             cudaFuncAttributeMaxDynamicSharedMemorySize, GEMM_SMEM);
    }

    float* ft;   cudaGetSymbolAddress((void**)&ft,   g_ft);
    float* xcat; cudaGetSymbolAddress((void**)&xcat, g_xcat);
    int*   cnt;  cudaGetSymbolAddress((void**)&cnt,  g_cnt);

    const int EB = 256;
    dim3 egrid((N_EDGES + EB - 1) / EB);
    dim3 wgrid(N_NODES / 8);          // 6250, warp-per-node kernels
    dim3 ggrid((N_NODES + 127) / 128);

    // ---- fork: CSR build on side stream s1 ----
    cudaEventRecord(ev_root, 0);
    cudaStreamWaitEvent(s1, ev_root, 0);
    cudaMemsetAsync(cnt, 0, N_NODES * sizeof(int), s1);
    k_hist<<<egrid, EB, 0, s1>>>(dst);
    k_scan1<<<SCAN_BLOCKS, 1024, 0, s1>>>();
    k_scan2<<<1, 32, 0, s1>>>();
    k_scan3<<<SCAN_BLOCKS, 1024, 0, s1>>>();
    k_scatter<<<egrid, EB, 0, s1>>>(src, dst, w);
    cudaEventRecord(ev_csr, s1);

    // ---- main stream: layer-1 GEMM + elr (independent of CSR) ----
    k_gemm_tf32<<<ggrid, GEMM_THREADS, GEMM_SMEM>>>(features, 256, W1, nullptr, ft, 128, N_NODES, 256);
    k_elr<<<wgrid, 256>>>(al1, ar1);

    // ---- join: agg needs CSR ----
    cudaStreamWaitEvent(0, ev_csr, 0);
    k_agg<<<wgrid, 256>>>(xcat, 256, 0);

    // layer 2
    k_gemm_tf32<<<ggrid, GEMM_THREADS, GEMM_SMEM>>>(xcat, 256, W2, nullptr, ft, 128, N_NODES, 128);
    k_elr<<<wgrid, 256>>>(al2, ar2);
    k_agg<<<wgrid, 256>>>(xcat, 256, 128);

    // output projection: [x1 | x2] @ Wout + bout
    k_gemm_tf32<<<ggrid, GEMM_THREADS, GEMM_SMEM>>>(xcat, 256, Wout, bout, out, 128, N_NODES, 256);
}

// round 13
// speedup vs baseline: 1.0421x; 1.0421x over previous
#include <cuda_runtime.h>
#include <cuda_bf16.h>
#include <math.h>
#include <stdint.h>

// ---------------------------------------------------------------------------
// GAT (2 layers) + output projection, GB300 sm_103a
// R13: (1) elr fused into GEMM epilogue (shfl-reduce over t4 quad, direct STG
//          — per-head dims live within one warp's column span, no atomics);
//      (2) output GEMM split: x1@Wout_top runs on side stream concurrent with
//          layer 2; x2@Wout_bot accumulates (beta=1) at the end.
// GEMM v4 core (tf32 HMMA, cp.async 3-stage, 2 CTAs/SM) + single-pass agg +
// forked CSR build unchanged (validated R10-R12).
// ---------------------------------------------------------------------------

#define N_NODES 50000
#define N_EDGES 400000
#define NEG_SLOPE 0.1f
#define SCAN_BLOCKS ((N_NODES + 1023) / 1024)   // 49

// -------------------- device scratch (no allocation allowed) ---------------
__device__ float g_ft[N_NODES * 128];      // per-layer transformed features
__device__ float g_xcat[N_NODES * 256];    // [x1 | x2] concat buffer
__device__ float g_el[N_NODES * 4];
__device__ float g_er[N_NODES * 4];
__device__ int   g_cnt[N_NODES];
__device__ int   g_bsum[SCAN_BLOCKS];
__device__ int   g_rowptr[N_NODES + 1];
__device__ int   g_epos[N_EDGES];          // per-edge ticket within its dst row
__device__ int   g_csr_src[N_EDGES];
__device__ float g_csr_w[N_EDGES];

// -------------------- CSR build --------------------------------------------
__global__ void k_hist(const int* __restrict__ dst) {
    int e = blockIdx.x * blockDim.x + threadIdx.x;
    if (e < N_EDGES) g_epos[e] = atomicAdd(&g_cnt[dst[e]], 1);
}

// coalesced 3-phase exclusive scan of g_cnt -> g_rowptr
__global__ void k_scan1() {
    __shared__ int sh[1024];
    int t = threadIdx.x;
    int i = blockIdx.x * 1024 + t;
    int v = (i < N_NODES) ? g_cnt[i] : 0;
    sh[t] = v;
    __syncthreads();
    for (int off = 1; off < 1024; off <<= 1) {
        int u = (t >= off) ? sh[t - off] : 0;
        __syncthreads();
        sh[t] += u;
        __syncthreads();
    }
    if (i < N_NODES) g_rowptr[i] = sh[t] - v;      // exclusive within block
    if (t == 1023) g_bsum[blockIdx.x] = sh[1023];  // block total
}

__global__ void k_scan2() {
    if (threadIdx.x == 0) {
        int run = 0;
        for (int b = 0; b < SCAN_BLOCKS; b++) {
            int v = g_bsum[b];
            g_bsum[b] = run;
            run += v;
        }
    }
}

__global__ void k_scan3() {
    int t = threadIdx.x;
    int i = blockIdx.x * 1024 + t;
    if (i < N_NODES) g_rowptr[i] += g_bsum[blockIdx.x];
    if (i == 0) g_rowptr[N_NODES] = N_EDGES;       // total is a known constant
}

__global__ void k_scatter(const int* __restrict__ src, const int* __restrict__ dst,
                          const float* __restrict__ w) {
    int e = blockIdx.x * blockDim.x + threadIdx.x;
    if (e >= N_EDGES) return;
    int pos = g_rowptr[dst[e]] + g_epos[e];
    g_csr_src[pos] = src[e];
    g_csr_w[pos]   = w[e];
}

// -------------------- tf32 tensor-core GEMM (cp.async pipeline) ------------
// C[M,128] = beta*C + A[M,K] @ B[K,128] (+bias), K multiple of 32.
// BM=128, BN=128, BK=32, 256 threads (8 warps, 4Mx2N), warp tile 32x64.
// 3-stage cp.async pipeline, ONE __syncthreads per tile, 2 CTAs/SM.
// Optional fused attention dots: el[r][h]=ft[r]·al[h], er likewise, computed
// from accumulator fragments (each head's 32 dims lie inside one warp's
// 64-col span -> shfl over t4 quad + direct STG, no smem/atomics).

#define GEMM_THREADS 256
#define AS_STRIDE 36            // words per A row  (+4 pad, 16B-aligned)
#define BS_STRIDE 136           // words per B row  (+8 pad, 16B-aligned)
#define ASZ_W (128 * AS_STRIDE) // 4608
#define BSZ_W (32 * BS_STRIDE)  // 4352
#define STAGE_W (ASZ_W + BSZ_W) // 8960 words = 35840 B
#define N_STAGES 3
#define GEMM_SMEM (N_STAGES * STAGE_W * 4)   // 107520 B per CTA

__device__ __forceinline__ uint32_t f2tf32(float x) {
    uint32_t r;
    asm("cvt.rna.tf32.f32 %0, %1;" : "=r"(r) : "f"(x));
    return r;
}

__device__ __forceinline__ void mma8(float* c, const uint32_t* a,
                                     uint32_t b0, uint32_t b1) {
    asm volatile(
        "mma.sync.aligned.m16n8k8.row.col.f32.tf32.tf32.f32 "
        "{%0,%1,%2,%3}, {%4,%5,%6,%7}, {%8,%9}, {%0,%1,%2,%3};"
        : "+f"(c[0]), "+f"(c[1]), "+f"(c[2]), "+f"(c[3])
        : "r"(a[0]), "r"(a[1]), "r"(a[2]), "r"(a[3]), "r"(b0), "r"(b1));
}

__device__ __forceinline__ uint32_t cvta_shared(const void* p) {
    uint32_t a;
    asm("{ .reg .u64 t; cvta.to.shared.u64 t, %1; cvt.u32.u64 %0, t; }"
        : "=r"(a) : "l"(p));
    return a;
}

__device__ __forceinline__ void cp16(uint32_t dst, const void* src, int sz) {
    asm volatile("cp.async.cg.shared.global [%0], [%1], 16, %2;"
                 :: "r"(dst), "l"(src), "r"(sz));
}

__global__ __launch_bounds__(GEMM_THREADS, 2) void k_gemm_tf32(
    const float* __restrict__ A, int lda,
    const float* __restrict__ B,
    const float* __restrict__ bias,
    const float* __restrict__ al,    // optional [128] attention left vec
    const float* __restrict__ arv,   // optional [128] attention right vec
    float* __restrict__ C, int ldc,
    int M, int K, int accum)
{
    extern __shared__ float smem[];
    const uint32_t sbase = cvta_shared(smem);

    const int tid  = threadIdx.x;
    const int lane = tid & 31;
    const int wid  = tid >> 5;
    const int warp_m = (wid & 3) * 32;     // 4 warps along M
    const int warp_n = (wid >> 2) * 64;    // 2 warps along N
    const int g  = lane >> 2;              // groupID (0..7)
    const int t4 = lane & 3;               // threadID_in_group
    const int row0 = blockIdx.x * 128;

    // per-thread cp.async coordinates (4 x 16B chunks each for A and B)
    int a_row[4], a_kq[4], b_row[4], b_c4[4];
    uint32_t a_dst[4], b_dst[4];
#pragma unroll
    for (int u = 0; u < 4; u++) {
        int c = tid + u * GEMM_THREADS;    // 0..1023
        a_row[u] = c >> 3;  a_kq[u] = c & 7;
        b_row[u] = c >> 5;  b_c4[u] = c & 31;
        a_dst[u] = sbase + (a_row[u] * AS_STRIDE + a_kq[u] * 4) * 4;
        b_dst[u] = sbase + (ASZ_W + b_row[u] * BS_STRIDE + b_c4[u] * 4) * 4;
    }

#define ISSUE_TILE(K0, st)                                                    \
    {                                                                         \
        uint32_t soff = (uint32_t)(st) * (STAGE_W * 4);                       \
        _Pragma("unroll")                                                     \
        for (int u = 0; u < 4; u++) {                                         \
            int gr = row0 + a_row[u];                                         \
            int ok = (gr < M) ? 16 : 0;                                       \
            const float* srcp = A + (size_t)min(gr, M - 1) * lda              \
                                  + (K0) + a_kq[u] * 4;                       \
            cp16(a_dst[u] + soff, srcp, ok);                                  \
        }                                                                     \
        _Pragma("unroll")                                                     \
        for (int u = 0; u < 4; u++) {                                         \
            const float* srcp = B + (size_t)((K0) + b_row[u]) * 128           \
                                  + b_c4[u] * 4;                              \
            cp16(b_dst[u] + soff, srcp, 16);                                  \
        }                                                                     \
        asm volatile("cp.async.commit_group;");                               \
    }

    float acc[2][8][4];
#pragma unroll
    for (int mt = 0; mt < 2; mt++)
#pragma unroll
        for (int nt = 0; nt < 8; nt++)
#pragma unroll
            for (int i = 0; i < 4; i++) acc[mt][nt][i] = 0.f;

    const int T = K >> 5;   // K/32 tiles

    // prologue: fill stages 0 and 1
    ISSUE_TILE(0, 0);
    if (T > 1) ISSUE_TILE(32, 1);

    for (int t = 0; t < T; t++) {
        if (t < T - 1) asm volatile("cp.async.wait_group 1;");
        else           asm volatile("cp.async.wait_group 0;");
        __syncthreads();
        // single barrier per tile: the ISSUE below writes stage
        // (t+2)%3 == (t-1)%3, whose readers (iteration t-1) all passed
        // this barrier already -> race-free without a second sync.

        const float* As_ = smem + (t % N_STAGES) * STAGE_W;
        const float* Bs_ = As_ + ASZ_W;

        if (t + 2 < T) ISSUE_TILE((t + 2) << 5, (t + 2) % N_STAGES);

#pragma unroll
        for (int ks = 0; ks < 4; ks++) {
            const int k8 = ks * 8;
            uint32_t a[2][4];
#pragma unroll
            for (int mt = 0; mt < 2; mt++) {
                int m_ = warp_m + mt * 16 + g;
                a[mt][0] = f2tf32(As_[m_ * AS_STRIDE + k8 + t4]);
                a[mt][1] = f2tf32(As_[(m_ + 8) * AS_STRIDE + k8 + t4]);
                a[mt][2] = f2tf32(As_[m_ * AS_STRIDE + k8 + t4 + 4]);
                a[mt][3] = f2tf32(As_[(m_ + 8) * AS_STRIDE + k8 + t4 + 4]);
            }
#pragma unroll
            for (int nt = 0; nt < 8; nt++) {
                int n_ = warp_n + nt * 8 + g;
                uint32_t b0 = f2tf32(Bs_[(k8 + t4) * BS_STRIDE + n_]);
                uint32_t b1 = f2tf32(Bs_[(k8 + t4 + 4) * BS_STRIDE + n_]);
                mma8(acc[0][nt], a[0], b0, b1);
                mma8(acc[1][nt], a[1], b0, b1);
            }
        }
    }

    // ---- fused attention dots (before bias / accum) ----
    if (al) {
        // idx = mt*4 + half*2 + hl  (hl = nt>>2: local head within warp span)
        float pel[8], per_[8];
#pragma unroll
        for (int i = 0; i < 8; i++) { pel[i] = 0.f; per_[i] = 0.f; }
#pragma unroll
        for (int nt = 0; nt < 8; nt++) {
            int c0 = warp_n + nt * 8 + t4 * 2;
            int hl = nt >> 2;
            float a0 = al[c0],  a1 = al[c0 + 1];
            float r0 = arv[c0], r1 = arv[c0 + 1];
#pragma unroll
            for (int mt = 0; mt < 2; mt++) {
                pel[mt * 4 + hl]      += acc[mt][nt][0] * a0 + acc[mt][nt][1] * a1;
                per_[mt * 4 + hl]     += acc[mt][nt][0] * r0 + acc[mt][nt][1] * r1;
                pel[mt * 4 + 2 + hl]  += acc[mt][nt][2] * a0 + acc[mt][nt][3] * a1;
                per_[mt * 4 + 2 + hl] += acc[mt][nt][2] * r0 + acc[mt][nt][3] * r1;
            }
        }
#pragma unroll
        for (int i = 0; i < 8; i++) {
            pel[i]  += __shfl_xor_sync(0xFFFFFFFFu, pel[i], 1);
            pel[i]  += __shfl_xor_sync(0xFFFFFFFFu, pel[i], 2);
            per_[i] += __shfl_xor_sync(0xFFFFFFFFu, per_[i], 1);
            per_[i] += __shfl_xor_sync(0xFFFFFFFFu, per_[i], 2);
        }
        if (t4 == 0) {
#pragma unroll
            for (int mt = 0; mt < 2; mt++)
#pragma unroll
                for (int half = 0; half < 2; half++)
#pragma unroll
                    for (int hl = 0; hl < 2; hl++) {
                        int r = row0 + warp_m + mt * 16 + half * 8 + g;
                        if (r < M) {
                            int h = (warp_n >> 5) + hl;   // 0,1 or 2,3
                            g_el[r * 4 + h] = pel[mt * 4 + half * 2 + hl];
                            g_er[r * 4 + h] = per_[mt * 4 + half * 2 + hl];
                        }
                    }
        }
    }

    // ---- epilogue ----
#pragma unroll
    for (int nt = 0; nt < 8; nt++) {
        int cg = warp_n + nt * 8 + t4 * 2;
        float bv0 = bias ? bias[cg]     : 0.f;
        float bv1 = bias ? bias[cg + 1] : 0.f;
#pragma unroll
        for (int mt = 0; mt < 2; mt++) {
            int r = row0 + warp_m + mt * 16 + g;
            if (r < M) {
                float2 o; o.x = acc[mt][nt][0] + bv0; o.y = acc[mt][nt][1] + bv1;
                if (accum) {
                    float2 old = *(float2*)(C + (size_t)r * ldc + cg);
                    o.x += old.x; o.y += old.y;
                }
                *(float2*)(C + (size_t)r * ldc + cg) = o;
            }
            if (r + 8 < M) {
                float2 o; o.x = acc[mt][nt][2] + bv0; o.y = acc[mt][nt][3] + bv1;
                if (accum) {
                    float2 old = *(float2*)(C + (size_t)(r + 8) * ldc + cg);
                    o.x += old.x; o.y += old.y;
                }
                *(float2*)(C + (size_t)(r + 8) * ldc + cg) = o;
            }
        }
    }
#undef ISSUE_TILE
}

// -------------------- softmax + aggregate: single gather pass --------------
// Logits z = w * leaky(el+er) are O(0.5) by construction, so softmax without
// max-subtraction is exact: exp(z)/sum(exp(z)). Accumulate unnormalized
// acc = sum(exp(z)*ft[src]) and csum = sum(exp(z)) together; scale at end.
__device__ __forceinline__ float leaky(float z) {
    return z > 0.f ? z : NEG_SLOPE * z;
}

__global__ __launch_bounds__(256) void k_agg(float* __restrict__ xout, int ld, int coff) {
    __shared__ float sh_c[8][32];
    __shared__ int   sh_s[8][8];

    int wid  = threadIdx.x >> 5;
    int lane = threadIdx.x & 31;
    int n = blockIdx.x * 8 + wid;
    if (n >= N_NODES) return;

    int beg = g_rowptr[n];
    int end = g_rowptr[n + 1];

    if (beg == end) {
#pragma unroll
        for (int j = 0; j < 4; j++)
            xout[(size_t)n * ld + coff + j * 32 + lane] = 0.f;
        return;
    }

    int h  = lane & 3;     // head evaluated by this lane (coeff phase)
    int es = lane >> 2;    // edge slot (0..7)
    float erh = g_er[n * 4 + h];

    float csum = 0.f;
    float acc[4] = {0.f, 0.f, 0.f, 0.f};

    for (int b = beg; b < end; b += 8) {
        int e = b + es;
        float c = 0.f;
        int   sn = 0;
        if (e < end) {
            sn = g_csr_src[e];
            float z = g_csr_w[e] * leaky(g_el[sn * 4 + h] + erh);
            c = expf(z);
            csum += c;
        }
        sh_c[wid][lane] = c;                 // slot es, head h (lane = es*4+h)
        if (h == 0) sh_s[wid][es] = sn;
        __syncwarp();
        // fixed 8-deep unroll: invalid slots have c=0 (contribute nothing) and
        // s=0 (harmless L1-hit read). Batches 32 LDGs for high MLP.
#pragma unroll
        for (int k = 0; k < 8; k++) {
            int s = sh_s[wid][k];
            const float* fp = g_ft + (size_t)s * 128 + lane;
            acc[0] += sh_c[wid][k * 4 + 0] * fp[0];
            acc[1] += sh_c[wid][k * 4 + 1] * fp[32];
            acc[2] += sh_c[wid][k * 4 + 2] * fp[64];
            acc[3] += sh_c[wid][k * 4 + 3] * fp[96];
        }
        __syncwarp();
    }

    csum += __shfl_xor_sync(0xFFFFFFFFu, csum, 4);
    csum += __shfl_xor_sync(0xFFFFFFFFu, csum, 8);
    csum += __shfl_xor_sync(0xFFFFFFFFu, csum, 16);
    float inv[4];
#pragma unroll
    for (int j = 0; j < 4; j++)
        inv[j] = 1.f / __shfl_sync(0xFFFFFFFFu, csum, j);

#pragma unroll
    for (int j = 0; j < 4; j++)
        xout[(size_t)n * ld + coff + j * 32 + lane] = fmaxf(acc[j] * inv[j], 0.f);
}

// -------------------- host launch ------------------------------------------
// Fork/join graph:
//   s1:   CSR build  ................ ev_csr
//   main: gemm1(+elr1 fused) -> [wait ev_csr] agg1 -> ev_x1
//   s1:   [wait ev_x1] gemm3a (x1@Wout_top + bout) -> ev_g3a
//   main: gemm2(+elr2 fused) -> agg2 -> [wait ev_g3a] gemm3b (out += x2@Wout_bot)
// Stream/events created once on the first (un-captured) call.

extern "C" void kernel_launch(void* const* d_in, const int* in_sizes, int n_in,
                              void* d_out, int out_size) {
    const float* features = (const float*)d_in[0];
    const int*   src      = (const int*)  d_in[1];
    const int*   dst      = (const int*)  d_in[2];
    const float* w        = (const float*)d_in[3];
    const float* W1       = (const float*)d_in[4];
    const float* al1      = (const float*)d_in[5];
    const float* ar1      = (const float*)d_in[6];
    const float* W2       = (const float*)d_in[7];
    const float* al2      = (const float*)d_in[8];
    const float* ar2      = (const float*)d_in[9];
    const float* Wout     = (const float*)d_in[10];
    const float* bout     = (const float*)d_in[11];
    float* out = (float*)d_out;

    static cudaStream_t s1 = nullptr;
    static cudaEvent_t  ev_root = nullptr, ev_csr = nullptr;
    static cudaEvent_t  ev_x1 = nullptr, ev_g3a = nullptr;
    if (s1 == nullptr) {
        cudaStreamCreateWithFlags(&s1, cudaStreamNonBlocking);
        cudaEventCreateWithFlags(&ev_root, cudaEventDisableTiming);
        cudaEventCreateWithFlags(&ev_csr,  cudaEventDisableTiming);
        cudaEventCreateWithFlags(&ev_x1,   cudaEventDisableTiming);
        cudaEventCreateWithFlags(&ev_g3a,  cudaEventDisableTiming);
        cudaFuncSetAttribute(k_gemm_tf32,
                             cudaFuncAttributeMaxDynamicSharedMemorySize, GEMM_SMEM);
    }

    float* ft;   cudaGetSymbolAddress((void**)&ft,   g_ft);
    float* xcat; cudaGetSymbolAddress((void**)&xcat, g_xcat);
    int*   cnt;  cudaGetSymbolAddress((void**)&cnt,  g_cnt);

    const int EB = 256;
    dim3 egrid((N_EDGES + EB - 1) / EB);
    dim3 wgrid(N_NODES / 8);          // 6250, warp-per-node kernels
    dim3 ggrid((N_NODES + 127) / 128);

    // ---- fork: CSR build on side stream s1 ----
    cudaEventRecord(ev_root, 0);
    cudaStreamWaitEvent(s1, ev_root, 0);
    cudaMemsetAsync(cnt, 0, N_NODES * sizeof(int), s1);
    k_hist<<<egrid, EB, 0, s1>>>(dst);
    k_scan1<<<SCAN_BLOCKS, 1024, 0, s1>>>();
    k_scan2<<<1, 32, 0, s1>>>();
    k_scan3<<<SCAN_BLOCKS, 1024, 0, s1>>>();
    k_scatter<<<egrid, EB, 0, s1>>>(src, dst, w);
    cudaEventRecord(ev_csr, s1);

    // ---- main: layer-1 GEMM with fused elr1 ----
    k_gemm_tf32<<<ggrid, GEMM_THREADS, GEMM_SMEM>>>(
        features, 256, W1, nullptr, al1, ar1, ft, 128, N_NODES, 256, 0);

    // ---- join CSR; aggregate layer 1 -> x1 (xcat cols 0..127) ----
    cudaStreamWaitEvent(0, ev_csr, 0);
    k_agg<<<wgrid, 256>>>(xcat, 256, 0);
    cudaEventRecord(ev_x1, 0);

    // ---- side stream: out = x1 @ Wout_top + bout (overlaps layer 2) ----
    cudaStreamWaitEvent(s1, ev_x1, 0);
    k_gemm_tf32<<<ggrid, GEMM_THREADS, GEMM_SMEM, s1>>>(
        xcat, 256, Wout, bout, nullptr, nullptr, out, 128, N_NODES, 128, 0);
    cudaEventRecord(ev_g3a, s1);

    // ---- main: layer-2 GEMM with fused elr2; aggregate -> x2 ----
    k_gemm_tf32<<<ggrid, GEMM_THREADS, GEMM_SMEM>>>(
        xcat, 256, W2, nullptr, al2, ar2, ft, 128, N_NODES, 128, 0);
    k_agg<<<wgrid, 256>>>(xcat, 256, 128);

    // ---- join; out += x2 @ Wout_bot ----
    cudaStreamWaitEvent(0, ev_g3a, 0);
    k_gemm_tf32<<<ggrid, GEMM_THREADS, GEMM_SMEM>>>(
        xcat + 128, 256, Wout + 128 * 128, nullptr, nullptr, nullptr,
        out, 128, N_NODES, 128, 1);
}